// round 4
// baseline (speedup 1.0000x reference)
#include <cuda_runtime.h>

#define MAXN 50000
#define MAXE 800000

// ---- scratch (static device globals; no allocation anywhere) ----
__device__ float g_y[MAXN * 256];      // GEMM out: [yl | yr] concat, up to 2*128 cols
__device__ float g_h[MAXN * 128];      // hidden activations between layers
__device__ float g_wcat[128 * 256];    // [Wl | Wr+Ws] per layer
__device__ float g_inv[MAXN];          // 1/max(deg,1)
__device__ int   g_deg[MAXN];
__device__ int   g_rowptr[MAXN + 1];
__device__ int   g_cursor[MAXN];
__device__ int   g_srcs[MAXE];         // src node per edge, grouped by dst (CSR payload)
__device__ int   g_is64;               // 1 if edge_index really is int64, 0 if int32

// ------------------------------------------------------------------
// Probe: decide whether edge_index is int64 or int32.
// Reads only the first 1024 int64 slots (8 KB) — in-bounds for either dtype.
__global__ void probe_kernel(const void* __restrict__ ei, int E, int N) {
    __shared__ int s_bad;
    if (threadIdx.x == 0) s_bad = 0;
    __syncthreads();
    const long long* p = (const long long*)ei;
    int nprobe = (E < 1024) ? E : 1024;
    for (int i = threadIdx.x; i < nprobe; i += blockDim.x) {
        long long v = p[i];
        if (v < 0 || v >= (long long)N) s_bad = 1;
    }
    __syncthreads();
    if (threadIdx.x == 0) g_is64 = s_bad ? 0 : 1;
}

__device__ __forceinline__ int edge_at(const void* ei, int E, int pos) {
    if (g_is64) return (int)((const long long*)ei)[pos];
    return ((const int*)ei)[pos];
}

// ------------------------------------------------------------------
__global__ void zero_deg_kernel(int n) {
    int i = blockIdx.x * blockDim.x + threadIdx.x;
    if (i < n) g_deg[i] = 0;
}

__global__ void cnt_kernel(const void* __restrict__ ei, int E, int N) {
    int e = blockIdx.x * blockDim.x + threadIdx.x;
    if (e < E) {
        int dst = edge_at(ei, E, E + e);
        if (dst >= 0 && dst < N) atomicAdd(&g_deg[dst], 1);
    }
}

// Single-block exclusive scan of g_deg -> g_rowptr/g_cursor; also g_inv.
__global__ __launch_bounds__(1024, 1)
void scan_kernel(int n) {
    __shared__ int warp_sums[32];
    __shared__ int s_carry;
    int tid = threadIdx.x, lane = tid & 31, wid = tid >> 5;
    if (tid == 0) s_carry = 0;
    __syncthreads();
    for (int base = 0; base < n; base += 1024) {
        int i = base + tid;
        int v = (i < n) ? g_deg[i] : 0;
        int x = v;
        #pragma unroll
        for (int o = 1; o < 32; o <<= 1) {
            int t = __shfl_up_sync(0xFFFFFFFFu, x, o);
            if (lane >= o) x += t;
        }
        if (lane == 31) warp_sums[wid] = x;
        __syncthreads();
        if (wid == 0) {
            int w = warp_sums[lane];
            #pragma unroll
            for (int o = 1; o < 32; o <<= 1) {
                int t = __shfl_up_sync(0xFFFFFFFFu, w, o);
                if (lane >= o) w += t;
            }
            warp_sums[lane] = w;
        }
        __syncthreads();
        int incl = x + (wid > 0 ? warp_sums[wid - 1] : 0);
        int excl = incl - v + s_carry;
        if (i < n) {
            g_rowptr[i] = excl;
            g_cursor[i] = excl;
            g_inv[i] = 1.0f / fmaxf((float)v, 1.0f);
        }
        __syncthreads();
        if (tid == 0) s_carry += warp_sums[31];
        __syncthreads();
    }
    if (threadIdx.x == 0) g_rowptr[n] = s_carry;
}

__global__ void fill_kernel(const void* __restrict__ ei, int E, int N) {
    int e = blockIdx.x * blockDim.x + threadIdx.x;
    if (e < E) {
        int src = edge_at(ei, E, e);
        int dst = edge_at(ei, E, E + e);
        if (src >= 0 && src < N && dst >= 0 && dst < N) {
            int pos = atomicAdd(&g_cursor[dst], 1);
            if (pos >= 0 && pos < E) g_srcs[pos] = src;
        }
    }
}

// g_wcat[k][j] = j<dout ? Wl[k][j] : Wr[k][j-dout] + Ws[k][j-dout]
__global__ void wcat_kernel(const float* __restrict__ Wl, const float* __restrict__ Wr,
                            const float* __restrict__ Ws, int dout) {
    int i = blockIdx.x * blockDim.x + threadIdx.x;
    int nc = 2 * dout;
    if (i < 128 * nc) {
        int k = i / nc, j = i - k * nc;
        g_wcat[i] = (j < dout) ? Wl[k * dout + j]
                               : (Wr[k * dout + (j - dout)] + Ws[k * dout + (j - dout)]);
    }
}

// ------------------------------------------------------------------
// SGEMM: g_y[M, NC] = A[M,128] @ g_wcat[128, NC].  Ain==nullptr -> read g_h.
// BM=128, BN=64, full-K tile in smem, 256 threads, TM=8 x TN=4.
__global__ __launch_bounds__(256, 2)
void gemm_kernel(const float* __restrict__ Ain, int M, int NC) {
    extern __shared__ float sm[];
    float* As = sm;              // [128 k][128 row] (transposed)
    float* Bs = sm + 128 * 128;  // [128 k][64 col]
    const float* A = Ain ? Ain : g_h;
    const int tid  = threadIdx.x;
    const int row0 = blockIdx.x * 128;
    const int col0 = blockIdx.y * 64;
    const int nc4  = NC >> 2;
    const float4* A4 = (const float4*)A;

    #pragma unroll
    for (int i = 0; i < 16; i++) {
        int idx = i * 256 + tid;
        int row = idx & 127;
        int kq  = idx >> 7;
        int gr  = row0 + row;
        float4 v = make_float4(0.f, 0.f, 0.f, 0.f);
        if (gr < M) v = A4[gr * 32 + kq];
        As[(kq * 4 + 0) * 128 + row] = v.x;
        As[(kq * 4 + 1) * 128 + row] = v.y;
        As[(kq * 4 + 2) * 128 + row] = v.z;
        As[(kq * 4 + 3) * 128 + row] = v.w;
    }
    const float4* B4 = (const float4*)g_wcat;
    #pragma unroll
    for (int i = 0; i < 8; i++) {
        int idx = i * 256 + tid;
        int kr = idx >> 4;
        int cq = idx & 15;
        *(float4*)&Bs[kr * 64 + cq * 4] = B4[kr * nc4 + (col0 >> 2) + cq];
    }
    __syncthreads();

    const int rg = (tid >> 4) * 8;
    const int cg = (tid & 15) * 4;
    float acc[8][4];
    #pragma unroll
    for (int i = 0; i < 8; i++)
        #pragma unroll
        for (int j = 0; j < 4; j++) acc[i][j] = 0.f;

    #pragma unroll 4
    for (int k = 0; k < 128; k++) {
        float4 b  = *(const float4*)&Bs[k * 64 + cg];
        float4 a0 = *(const float4*)&As[k * 128 + rg];
        float4 a1 = *(const float4*)&As[k * 128 + rg + 4];
        float a[8] = {a0.x, a0.y, a0.z, a0.w, a1.x, a1.y, a1.z, a1.w};
        #pragma unroll
        for (int i = 0; i < 8; i++) {
            acc[i][0] += a[i] * b.x;
            acc[i][1] += a[i] * b.y;
            acc[i][2] += a[i] * b.z;
            acc[i][3] += a[i] * b.w;
        }
    }

    float4* C4 = (float4*)g_y;
    #pragma unroll
    for (int i = 0; i < 8; i++) {
        int r = row0 + rg + i;
        if (r < M)
            C4[r * nc4 + ((col0 + cg) >> 2)] =
                make_float4(acc[i][0], acc[i][1], acc[i][2], acc[i][3]);
    }
}

// ------------------------------------------------------------------
// Fused gather-aggregate + mean + residual + bias (+relu).
// DOUTQ lanes per node; lane q owns float4 chunk q of the feature row.
template <int DOUTQ>
__global__ void agg_kernel(const float* __restrict__ bl, const float* __restrict__ bs,
                           float* __restrict__ outp, int N, int do_relu) {
    const int ld4 = 2 * DOUTQ;           // row stride of g_y in float4s
    int gt = blockIdx.x * blockDim.x + threadIdx.x;
    int n  = gt / DOUTQ;
    int q  = gt & (DOUTQ - 1);
    if (n >= N) return;

    int beg = g_rowptr[n];
    int end = g_rowptr[n + 1];
    const float4* Y = (const float4*)g_y;

    float4 a0 = make_float4(0.f, 0.f, 0.f, 0.f);
    float4 a1 = make_float4(0.f, 0.f, 0.f, 0.f);
    int j = beg;
    for (; j + 1 < end; j += 2) {
        int s0 = g_srcs[j];
        int s1 = g_srcs[j + 1];
        float4 v0 = Y[s0 * ld4 + q];
        float4 v1 = Y[s1 * ld4 + q];
        a0.x += v0.x; a0.y += v0.y; a0.z += v0.z; a0.w += v0.w;
        a1.x += v1.x; a1.y += v1.y; a1.z += v1.z; a1.w += v1.w;
    }
    if (j < end) {
        int s0 = g_srcs[j];
        float4 v0 = Y[s0 * ld4 + q];
        a0.x += v0.x; a0.y += v0.y; a0.z += v0.z; a0.w += v0.w;
    }
    a0.x += a1.x; a0.y += a1.y; a0.z += a1.z; a0.w += a1.w;

    float inv = g_inv[n];
    float4 yr = Y[n * ld4 + DOUTQ + q];
    float4 b1 = ((const float4*)bl)[q];
    float4 b2 = ((const float4*)bs)[q];
    float4 o;
    o.x = fmaf(a0.x, inv, yr.x) + b1.x + b2.x;
    o.y = fmaf(a0.y, inv, yr.y) + b1.y + b2.y;
    o.z = fmaf(a0.z, inv, yr.z) + b1.z + b2.z;
    o.w = fmaf(a0.w, inv, yr.w) + b1.w + b2.w;
    if (do_relu) {
        o.x = fmaxf(o.x, 0.f); o.y = fmaxf(o.y, 0.f);
        o.z = fmaxf(o.z, 0.f); o.w = fmaxf(o.w, 0.f);
    }
    float4* O = outp ? (float4*)outp : (float4*)g_h;
    O[n * DOUTQ + q] = o;
}

// ------------------------------------------------------------------
extern "C" void kernel_launch(void* const* d_in, const int* in_sizes, int n_in,
                              void* d_out, int out_size) {
    const float* x  = (const float*)d_in[0];
    const void*  ei = d_in[1];   // int64 OR int32 edge_index [2, E] — probed at runtime
    const float* Wl[3] = {(const float*)d_in[4],  (const float*)d_in[9],  (const float*)d_in[14]};
    const float* bl[3] = {(const float*)d_in[5],  (const float*)d_in[10], (const float*)d_in[15]};
    const float* Wr[3] = {(const float*)d_in[6],  (const float*)d_in[11], (const float*)d_in[16]};
    const float* Ws[3] = {(const float*)d_in[7],  (const float*)d_in[12], (const float*)d_in[17]};
    const float* bs[3] = {(const float*)d_in[8],  (const float*)d_in[13], (const float*)d_in[18]};

    int N = in_sizes[0] / 128;
    int E = in_sizes[1] / 2;

    cudaFuncSetAttribute(gemm_kernel, cudaFuncAttributeMaxDynamicSharedMemorySize, 98304);

    // ---- CSR build (layer-invariant) ----
    probe_kernel<<<1, 256>>>(ei, E, N);
    zero_deg_kernel<<<(N + 255) / 256, 256>>>(N);
    cnt_kernel<<<(E + 255) / 256, 256>>>(ei, E, N);
    scan_kernel<<<1, 1024>>>(N);
    fill_kernel<<<(E + 255) / 256, 256>>>(ei, E, N);

    const int douts[3] = {128, 128, 64};
    for (int L = 0; L < 3; L++) {
        int dout  = douts[L];
        int nc    = 2 * dout;
        int doutq = dout / 4;

        wcat_kernel<<<(128 * nc + 255) / 256, 256>>>(Wl[L], Wr[L], Ws[L], dout);

        dim3 gg((N + 127) / 128, nc / 64);
        gemm_kernel<<<gg, 256, 98304>>>(L == 0 ? x : nullptr, N, nc);

        float* outp = (L == 2) ? (float*)d_out : nullptr;
        int threads = N * doutq;
        if (dout == 128)
            agg_kernel<32><<<(threads + 255) / 256, 256>>>(bl[L], bs[L], outp, N, 1);
        else
            agg_kernel<16><<<(threads + 255) / 256, 256>>>(bl[L], bs[L], outp, N, 0);
    }
}

// round 7
// speedup vs baseline: 1.8831x; 1.8831x over previous
#include <cuda_runtime.h>
#include <cstdint>

#define MAXN 50000
#define MAXE 800000
#define SCAN_BLK 1024
#define NBLK_SCAN ((MAXN + SCAN_BLK - 1) / SCAN_BLK)

// ---- scratch (static device globals; no allocation anywhere) ----
__device__ float g_y[MAXN * 256];       // GEMM out: [yl | yr] concat
__device__ float g_h[MAXN * 128];       // hidden activations
__device__ float g_wcatT[256 * 128];    // B^T: [NC rows][128 K]
__device__ float g_inv[MAXN];
__device__ int   g_deg[MAXN];
__device__ int   g_rowptr[MAXN + 1];
__device__ int   g_cursor[MAXN];
__device__ int   g_srcs[MAXE];
__device__ int   g_is64;
__device__ int   g_bsum[NBLK_SCAN + 1];

// ================= CSR build =================
__global__ void probe_kernel(const void* __restrict__ ei, int E, int N) {
    __shared__ int s_bad;
    if (threadIdx.x == 0) s_bad = 0;
    __syncthreads();
    const long long* p = (const long long*)ei;
    int nprobe = (E < 1024) ? E : 1024;
    for (int i = threadIdx.x; i < nprobe; i += blockDim.x) {
        long long v = p[i];
        if (v < 0 || v >= (long long)N) s_bad = 1;
    }
    __syncthreads();
    if (threadIdx.x == 0) g_is64 = s_bad ? 0 : 1;
}

__device__ __forceinline__ int edge_at(const void* ei, int E, int pos) {
    if (g_is64) return (int)((const long long*)ei)[pos];
    return ((const int*)ei)[pos];
}

__global__ void zero_deg_kernel(int n) {
    int i = blockIdx.x * blockDim.x + threadIdx.x;
    if (i < n) g_deg[i] = 0;
}

__global__ void cnt_kernel(const void* __restrict__ ei, int E, int N) {
    int e = blockIdx.x * blockDim.x + threadIdx.x;
    if (e < E) {
        int dst = edge_at(ei, E, E + e);
        if (dst >= 0 && dst < N) atomicAdd(&g_deg[dst], 1);
    }
}

__device__ __forceinline__ int block_scan_incl(int v, int* warp_sums) {
    int lane = threadIdx.x & 31, wid = threadIdx.x >> 5;
    int x = v;
    #pragma unroll
    for (int o = 1; o < 32; o <<= 1) {
        int t = __shfl_up_sync(0xFFFFFFFFu, x, o);
        if (lane >= o) x += t;
    }
    if (lane == 31) warp_sums[wid] = x;
    __syncthreads();
    if (wid == 0) {
        int nw = (blockDim.x + 31) >> 5;
        int w = (lane < nw) ? warp_sums[lane] : 0;
        #pragma unroll
        for (int o = 1; o < 32; o <<= 1) {
            int t = __shfl_up_sync(0xFFFFFFFFu, w, o);
            if (lane >= o) w += t;
        }
        warp_sums[lane] = w;
    }
    __syncthreads();
    return x + (wid > 0 ? warp_sums[wid - 1] : 0);
}

__global__ __launch_bounds__(SCAN_BLK, 1)
void scan1_kernel(int n) {
    __shared__ int warp_sums[32];
    int i = blockIdx.x * SCAN_BLK + threadIdx.x;
    int v = (i < n) ? g_deg[i] : 0;
    int incl = block_scan_incl(v, warp_sums);
    if (i < n) g_rowptr[i] = incl - v;
    if (threadIdx.x == SCAN_BLK - 1) g_bsum[blockIdx.x] = incl;
}

__global__ __launch_bounds__(SCAN_BLK, 1)
void scan2_kernel(int nb) {
    __shared__ int warp_sums[32];
    int t = threadIdx.x;
    int v = (t < nb) ? g_bsum[t] : 0;
    int incl = block_scan_incl(v, warp_sums);
    if (t < nb) g_bsum[t] = incl - v;
    if (t == nb - 1) g_bsum[nb] = incl;
}

__global__ __launch_bounds__(SCAN_BLK, 1)
void scan3_kernel(int n) {
    int i = blockIdx.x * SCAN_BLK + threadIdx.x;
    if (i < n) {
        int r = g_rowptr[i] + g_bsum[blockIdx.x];
        g_rowptr[i] = r;
        g_cursor[i] = r;
        g_inv[i] = 1.0f / fmaxf((float)g_deg[i], 1.0f);
    }
    if (blockIdx.x == 0 && threadIdx.x == 0)
        g_rowptr[n] = g_bsum[(n + SCAN_BLK - 1) / SCAN_BLK];
}

__global__ void fill_kernel(const void* __restrict__ ei, int E, int N) {
    int e = blockIdx.x * blockDim.x + threadIdx.x;
    if (e < E) {
        int src = edge_at(ei, E, e);
        int dst = edge_at(ei, E, E + e);
        if (src >= 0 && src < N && dst >= 0 && dst < N) {
            int pos = atomicAdd(&g_cursor[dst], 1);
            if (pos >= 0 && pos < E) g_srcs[pos] = src;
        }
    }
}

// g_wcatT[j][k] = j<dout ? Wl[k][j] : Wr[k][j-dout] + Ws[k][j-dout]
__global__ void wcatT_kernel(const float* __restrict__ Wl, const float* __restrict__ Wr,
                             const float* __restrict__ Ws, int dout) {
    int i = blockIdx.x * blockDim.x + threadIdx.x;  // i = j*128 + k
    int nc = 2 * dout;
    if (i < nc * 128) {
        int j = i >> 7, k = i & 127;
        g_wcatT[i] = (j < dout) ? Wl[k * dout + j]
                                : (Wr[k * dout + (j - dout)] + Ws[k * dout + (j - dout)]);
    }
}

// ================= tf32 mma.sync GEMM =================
// g_y[M, NC] tile = A[row0:+128, :] @ wcatT[col0:+64, :]^T
// 256 threads = 8 warps (4 along M x 2 along N); warp tile 32x32.
// smem stride 132 floats -> conflict-free fragment LDS.

__device__ __forceinline__ uint32_t f2tf32(float f) {
    uint32_t u;
    asm("cvt.rna.tf32.f32 %0, %1;" : "=r"(u) : "f"(f));
    return u;
}

__device__ __forceinline__ void mma16n8k8(float* c, const uint32_t* a, const uint32_t* b) {
    asm volatile(
        "mma.sync.aligned.m16n8k8.row.col.f32.tf32.tf32.f32 "
        "{%0,%1,%2,%3}, {%4,%5,%6,%7}, {%8,%9}, {%0,%1,%2,%3};"
        : "+f"(c[0]), "+f"(c[1]), "+f"(c[2]), "+f"(c[3])
        : "r"(a[0]), "r"(a[1]), "r"(a[2]), "r"(a[3]), "r"(b[0]), "r"(b[1]));
}

#define ASTRIDE 132
static constexpr int GSM_BYTES = (128 * ASTRIDE + 64 * ASTRIDE) * 4;  // 101376

__global__ __launch_bounds__(256, 2)
void mma_gemm_kernel(const float* __restrict__ Ain, int M, int NC) {
    extern __shared__ uint32_t sm[];
    uint32_t* As = sm;                    // [128][132] tf32 bits
    uint32_t* Bs = sm + 128 * ASTRIDE;    // [64][132]
    const float* A = Ain ? Ain : g_h;
    const int tid = threadIdx.x;
    const int warp = tid >> 5;
    const int lane = tid & 31;
    const int warpM = warp & 3;           // 0..3
    const int warpN = warp >> 2;          // 0..1
    const int row0 = blockIdx.x * 128;
    const int col0 = blockIdx.y * 64;

    // ---- load A tile (128 rows x 128 K), convert to tf32 ----
    const float4* A4 = (const float4*)A;
    #pragma unroll
    for (int i = 0; i < 16; i++) {
        int idx = i * 256 + tid;
        int row = idx >> 5;          // 0..127
        int q   = idx & 31;          // float4 index along K
        float4 v = make_float4(0.f, 0.f, 0.f, 0.f);
        int gr = row0 + row;
        if (gr < M) v = A4[gr * 32 + q];
        uint32_t* p = &As[row * ASTRIDE + q * 4];
        p[0] = f2tf32(v.x); p[1] = f2tf32(v.y); p[2] = f2tf32(v.z); p[3] = f2tf32(v.w);
    }
    // ---- load B tile (64 rows x 128 K) from g_wcatT ----
    const float4* W4 = (const float4*)g_wcatT;
    #pragma unroll
    for (int i = 0; i < 8; i++) {
        int idx = i * 256 + tid;
        int row = idx >> 5;          // 0..63
        int q   = idx & 31;
        float4 v = W4[(col0 + row) * 32 + q];
        uint32_t* p = &Bs[row * ASTRIDE + q * 4];
        p[0] = f2tf32(v.x); p[1] = f2tf32(v.y); p[2] = f2tf32(v.z); p[3] = f2tf32(v.w);
    }
    __syncthreads();

    float c[2][4][4];
    #pragma unroll
    for (int mt = 0; mt < 2; mt++)
        #pragma unroll
        for (int nt = 0; nt < 4; nt++)
            #pragma unroll
            for (int j = 0; j < 4; j++) c[mt][nt][j] = 0.f;

    const int rA = warpM * 32 + (lane >> 2);
    const int nB = warpN * 32 + (lane >> 2);
    const int kq = lane & 3;

    #pragma unroll
    for (int ks = 0; ks < 16; ks++) {
        const int k0 = ks * 8 + kq;
        uint32_t a[2][4], b[4][2];
        #pragma unroll
        for (int mt = 0; mt < 2; mt++) {
            int r = rA + mt * 16;
            a[mt][0] = As[r * ASTRIDE + k0];
            a[mt][1] = As[(r + 8) * ASTRIDE + k0];
            a[mt][2] = As[r * ASTRIDE + k0 + 4];
            a[mt][3] = As[(r + 8) * ASTRIDE + k0 + 4];
        }
        #pragma unroll
        for (int nt = 0; nt < 4; nt++) {
            int n = nB + nt * 8;
            b[nt][0] = Bs[n * ASTRIDE + k0];
            b[nt][1] = Bs[n * ASTRIDE + k0 + 4];
        }
        #pragma unroll
        for (int mt = 0; mt < 2; mt++)
            #pragma unroll
            for (int nt = 0; nt < 4; nt++)
                mma16n8k8(c[mt][nt], a[mt], b[nt]);
    }

    // ---- epilogue: fragment layout stores (float2, coalesced within quad) ----
    #pragma unroll
    for (int mt = 0; mt < 2; mt++) {
        int r_lo = row0 + warpM * 32 + mt * 16 + (lane >> 2);
        #pragma unroll
        for (int nt = 0; nt < 4; nt++) {
            int col = col0 + warpN * 32 + nt * 8 + 2 * (lane & 3);
            if (r_lo < M)
                *(float2*)&g_y[r_lo * NC + col] = make_float2(c[mt][nt][0], c[mt][nt][1]);
            if (r_lo + 8 < M)
                *(float2*)&g_y[(r_lo + 8) * NC + col] = make_float2(c[mt][nt][2], c[mt][nt][3]);
        }
    }
}

// ================= fused aggregation epilogue =================
template <int DOUTQ>
__global__ void agg_kernel(const float* __restrict__ bl, const float* __restrict__ bs,
                           float* __restrict__ outp, int N, int do_relu) {
    const int ld4 = 2 * DOUTQ;
    int gt = blockIdx.x * blockDim.x + threadIdx.x;
    int n  = gt / DOUTQ;
    int q  = gt & (DOUTQ - 1);
    if (n >= N) return;

    int beg = g_rowptr[n];
    int end = g_rowptr[n + 1];
    const float4* Y = (const float4*)g_y;

    float4 a0 = make_float4(0.f, 0.f, 0.f, 0.f);
    float4 a1 = make_float4(0.f, 0.f, 0.f, 0.f);
    int j = beg;
    for (; j + 1 < end; j += 2) {
        int s0 = g_srcs[j];
        int s1 = g_srcs[j + 1];
        float4 v0 = Y[s0 * ld4 + q];
        float4 v1 = Y[s1 * ld4 + q];
        a0.x += v0.x; a0.y += v0.y; a0.z += v0.z; a0.w += v0.w;
        a1.x += v1.x; a1.y += v1.y; a1.z += v1.z; a1.w += v1.w;
    }
    if (j < end) {
        int s0 = g_srcs[j];
        float4 v0 = Y[s0 * ld4 + q];
        a0.x += v0.x; a0.y += v0.y; a0.z += v0.z; a0.w += v0.w;
    }
    a0.x += a1.x; a0.y += a1.y; a0.z += a1.z; a0.w += a1.w;

    float inv = g_inv[n];
    float4 yr = Y[n * ld4 + DOUTQ + q];
    float4 b1 = ((const float4*)bl)[q];
    float4 b2 = ((const float4*)bs)[q];
    float4 o;
    o.x = fmaf(a0.x, inv, yr.x) + b1.x + b2.x;
    o.y = fmaf(a0.y, inv, yr.y) + b1.y + b2.y;
    o.z = fmaf(a0.z, inv, yr.z) + b1.z + b2.z;
    o.w = fmaf(a0.w, inv, yr.w) + b1.w + b2.w;
    if (do_relu) {
        o.x = fmaxf(o.x, 0.f); o.y = fmaxf(o.y, 0.f);
        o.z = fmaxf(o.z, 0.f); o.w = fmaxf(o.w, 0.f);
    }
    float4* O = outp ? (float4*)outp : (float4*)g_h;
    O[n * DOUTQ + q] = o;
}

// ================= host launch =================
extern "C" void kernel_launch(void* const* d_in, const int* in_sizes, int n_in,
                              void* d_out, int out_size) {
    const float* x  = (const float*)d_in[0];
    const void*  ei = d_in[1];
    const float* Wl[3] = {(const float*)d_in[4],  (const float*)d_in[9],  (const float*)d_in[14]};
    const float* bl[3] = {(const float*)d_in[5],  (const float*)d_in[10], (const float*)d_in[15]};
    const float* Wr[3] = {(const float*)d_in[6],  (const float*)d_in[11], (const float*)d_in[16]};
    const float* Ws[3] = {(const float*)d_in[7],  (const float*)d_in[12], (const float*)d_in[17]};
    const float* bs[3] = {(const float*)d_in[8],  (const float*)d_in[13], (const float*)d_in[18]};

    int N = in_sizes[0] / 128;
    int E = in_sizes[1] / 2;

    cudaFuncSetAttribute(mma_gemm_kernel, cudaFuncAttributeMaxDynamicSharedMemorySize, GSM_BYTES);

    // ---- CSR build ----
    probe_kernel<<<1, 256>>>(ei, E, N);
    zero_deg_kernel<<<(N + 255) / 256, 256>>>(N);
    cnt_kernel<<<(E + 255) / 256, 256>>>(ei, E, N);
    int nb = (N + SCAN_BLK - 1) / SCAN_BLK;
    scan1_kernel<<<nb, SCAN_BLK>>>(N);
    scan2_kernel<<<1, SCAN_BLK>>>(nb);
    scan3_kernel<<<nb, SCAN_BLK>>>(N);
    fill_kernel<<<(E + 255) / 256, 256>>>(ei, E, N);

    const int douts[3] = {128, 128, 64};
    for (int L = 0; L < 3; L++) {
        int dout  = douts[L];
        int nc    = 2 * dout;
        int doutq = dout / 4;

        wcatT_kernel<<<(nc * 128 + 255) / 256, 256>>>(Wl[L], Wr[L], Ws[L], dout);

        dim3 gg((N + 127) / 128, nc / 64);
        mma_gemm_kernel<<<gg, 256, GSM_BYTES>>>(L == 0 ? x : nullptr, N, nc);

        float* outp = (L == 2) ? (float*)d_out : nullptr;
        int threads = N * doutq;
        if (dout == 128)
            agg_kernel<32><<<(threads + 255) / 256, 256>>>(bl[L], bs[L], outp, N, 1);
        else
            agg_kernel<16><<<(threads + 255) / 256, 256>>>(bl[L], bs[L], outp, N, 0);
    }
}

// round 8
// speedup vs baseline: 2.1220x; 1.1269x over previous
#include <cuda_runtime.h>
#include <cuda_fp16.h>
#include <cstdint>

#define MAXN 50000
#define MAXE 800000
#define SCAN_BLK 1024
#define NBLK_SCAN ((MAXN + SCAN_BLK - 1) / SCAN_BLK)

// ---- scratch (static device globals; no allocation anywhere) ----
__device__ __half g_yl[MAXN * 128];     // aggregation operand (lin_l path), fp16
__device__ float  g_yr[MAXN * 128];     // residual path (Wr+Ws), fp32
__device__ float  g_h[MAXN * 128];      // hidden activations (GEMM input), fp32
__device__ float  g_wcatT3[640 * 128];  // B^T for all 3 layers: [nc rows][128 K] each
__device__ float  g_inv[MAXN];
__device__ int    g_deg[MAXN];
__device__ int    g_rowptr[MAXN + 1];
__device__ int    g_cursor[MAXN];
__device__ int    g_srcs[MAXE];
__device__ int    g_is64;
__device__ int    g_bsum[NBLK_SCAN + 1];

// ================= CSR build =================
__global__ void probe_kernel(const void* __restrict__ ei, int E, int N) {
    __shared__ int s_bad;
    if (threadIdx.x == 0) s_bad = 0;
    __syncthreads();
    const long long* p = (const long long*)ei;
    int nprobe = (E < 1024) ? E : 1024;
    for (int i = threadIdx.x; i < nprobe; i += blockDim.x) {
        long long v = p[i];
        if (v < 0 || v >= (long long)N) s_bad = 1;
    }
    __syncthreads();
    if (threadIdx.x == 0) g_is64 = s_bad ? 0 : 1;
}

__device__ __forceinline__ int edge_at(const void* ei, int E, int pos) {
    if (g_is64) return (int)((const long long*)ei)[pos];
    return ((const int*)ei)[pos];
}

__global__ void zero_deg_kernel(int n) {
    int i = blockIdx.x * blockDim.x + threadIdx.x;
    if (i < n) g_deg[i] = 0;
}

__global__ void cnt_kernel(const void* __restrict__ ei, int E, int N) {
    int e = blockIdx.x * blockDim.x + threadIdx.x;
    if (e < E) {
        int dst = edge_at(ei, E, E + e);
        if (dst >= 0 && dst < N) atomicAdd(&g_deg[dst], 1);
    }
}

__device__ __forceinline__ int block_scan_incl(int v, int* warp_sums) {
    int lane = threadIdx.x & 31, wid = threadIdx.x >> 5;
    int x = v;
    #pragma unroll
    for (int o = 1; o < 32; o <<= 1) {
        int t = __shfl_up_sync(0xFFFFFFFFu, x, o);
        if (lane >= o) x += t;
    }
    if (lane == 31) warp_sums[wid] = x;
    __syncthreads();
    if (wid == 0) {
        int nw = (blockDim.x + 31) >> 5;
        int w = (lane < nw) ? warp_sums[lane] : 0;
        #pragma unroll
        for (int o = 1; o < 32; o <<= 1) {
            int t = __shfl_up_sync(0xFFFFFFFFu, w, o);
            if (lane >= o) w += t;
        }
        warp_sums[lane] = w;
    }
    __syncthreads();
    return x + (wid > 0 ? warp_sums[wid - 1] : 0);
}

__global__ __launch_bounds__(SCAN_BLK, 1)
void scan1_kernel(int n) {
    __shared__ int warp_sums[32];
    int i = blockIdx.x * SCAN_BLK + threadIdx.x;
    int v = (i < n) ? g_deg[i] : 0;
    int incl = block_scan_incl(v, warp_sums);
    if (i < n) g_rowptr[i] = incl - v;
    if (threadIdx.x == SCAN_BLK - 1) g_bsum[blockIdx.x] = incl;
}

__global__ __launch_bounds__(SCAN_BLK, 1)
void scan2_kernel(int nb) {
    __shared__ int warp_sums[32];
    int t = threadIdx.x;
    int v = (t < nb) ? g_bsum[t] : 0;
    int incl = block_scan_incl(v, warp_sums);
    if (t < nb) g_bsum[t] = incl - v;
    if (t == nb - 1) g_bsum[nb] = incl;
}

__global__ __launch_bounds__(SCAN_BLK, 1)
void scan3_kernel(int n) {
    int i = blockIdx.x * SCAN_BLK + threadIdx.x;
    if (i < n) {
        int r = g_rowptr[i] + g_bsum[blockIdx.x];
        g_rowptr[i] = r;
        g_cursor[i] = r;
        g_inv[i] = 1.0f / fmaxf((float)g_deg[i], 1.0f);
    }
    if (blockIdx.x == 0 && threadIdx.x == 0)
        g_rowptr[n] = g_bsum[(n + SCAN_BLK - 1) / SCAN_BLK];
}

__global__ void fill_kernel(const void* __restrict__ ei, int E, int N) {
    int e = blockIdx.x * blockDim.x + threadIdx.x;
    if (e < E) {
        int src = edge_at(ei, E, e);
        int dst = edge_at(ei, E, E + e);
        if (src >= 0 && src < N && dst >= 0 && dst < N) {
            int pos = atomicAdd(&g_cursor[dst], 1);
            if (pos >= 0 && pos < E) g_srcs[pos] = src;
        }
    }
}

// ================= fused weight prep (all 3 layers, layer-invariant) =================
// layout: L0 rows [0,256), L1 rows [256,512), L2 rows [512,640)
// row j of layer L: j<dout ? Wl[:,j] : Wr[:,j-dout]+Ws[:,j-dout], K-major (128)
__global__ void wcat_all_kernel(const float* __restrict__ Wl0, const float* __restrict__ Wr0, const float* __restrict__ Ws0,
                                const float* __restrict__ Wl1, const float* __restrict__ Wr1, const float* __restrict__ Ws1,
                                const float* __restrict__ Wl2, const float* __restrict__ Wr2, const float* __restrict__ Ws2) {
    int i = blockIdx.x * blockDim.x + threadIdx.x;   // i = grow*128 + k
    if (i >= 640 * 128) return;
    int grow = i >> 7, k = i & 127;
    const float *Wl, *Wr, *Ws;
    int j, dout;
    if (grow < 256)      { Wl = Wl0; Wr = Wr0; Ws = Ws0; j = grow;       dout = 128; }
    else if (grow < 512) { Wl = Wl1; Wr = Wr1; Ws = Ws1; j = grow - 256; dout = 128; }
    else                 { Wl = Wl2; Wr = Wr2; Ws = Ws2; j = grow - 512; dout = 64;  }
    g_wcatT3[i] = (j < dout) ? Wl[k * dout + j]
                             : (Wr[k * dout + (j - dout)] + Ws[k * dout + (j - dout)]);
}

// ================= tf32 mma.sync GEMM =================
// tile D[128,64] = A[row0:+128, :] @ wcatT[wrow0+col0 :+64, :]^T
// epilogue: cols < dout -> g_yl (fp16), cols >= dout -> g_yr (fp32)
__device__ __forceinline__ uint32_t f2tf32(float f) {
    uint32_t u;
    asm("cvt.rna.tf32.f32 %0, %1;" : "=r"(u) : "f"(f));
    return u;
}

__device__ __forceinline__ void mma16n8k8(float* c, const uint32_t* a, const uint32_t* b) {
    asm volatile(
        "mma.sync.aligned.m16n8k8.row.col.f32.tf32.tf32.f32 "
        "{%0,%1,%2,%3}, {%4,%5,%6,%7}, {%8,%9}, {%0,%1,%2,%3};"
        : "+f"(c[0]), "+f"(c[1]), "+f"(c[2]), "+f"(c[3])
        : "r"(a[0]), "r"(a[1]), "r"(a[2]), "r"(a[3]), "r"(b[0]), "r"(b[1]));
}

#define ASTRIDE 132
static constexpr int GSM_BYTES = (128 * ASTRIDE + 64 * ASTRIDE) * 4;  // 101376

__global__ __launch_bounds__(256, 2)
void mma_gemm_kernel(const float* __restrict__ Ain, int M, int dout, int wrow0) {
    extern __shared__ uint32_t sm[];
    uint32_t* As = sm;                    // [128][132] tf32 bits
    uint32_t* Bs = sm + 128 * ASTRIDE;    // [64][132]
    const float* A = Ain ? Ain : g_h;
    const int tid = threadIdx.x;
    const int warp = tid >> 5;
    const int lane = tid & 31;
    const int warpM = warp & 3;           // 0..3
    const int warpN = warp >> 2;          // 0..1
    const int row0 = blockIdx.x * 128;
    const int col0 = blockIdx.y * 64;

    // ---- load A tile (128 x 128 K) -> tf32 smem ----
    const float4* A4 = (const float4*)A;
    #pragma unroll
    for (int i = 0; i < 16; i++) {
        int idx = i * 256 + tid;
        int row = idx >> 5;
        int q   = idx & 31;
        float4 v = make_float4(0.f, 0.f, 0.f, 0.f);
        int gr = row0 + row;
        if (gr < M) v = A4[gr * 32 + q];
        uint32_t* p = &As[row * ASTRIDE + q * 4];
        p[0] = f2tf32(v.x); p[1] = f2tf32(v.y); p[2] = f2tf32(v.z); p[3] = f2tf32(v.w);
    }
    // ---- load B tile (64 x 128 K) from g_wcatT3 ----
    const float4* W4 = (const float4*)g_wcatT3;
    #pragma unroll
    for (int i = 0; i < 8; i++) {
        int idx = i * 256 + tid;
        int row = idx >> 5;
        int q   = idx & 31;
        float4 v = W4[(wrow0 + col0 + row) * 32 + q];
        uint32_t* p = &Bs[row * ASTRIDE + q * 4];
        p[0] = f2tf32(v.x); p[1] = f2tf32(v.y); p[2] = f2tf32(v.z); p[3] = f2tf32(v.w);
    }
    __syncthreads();

    float c[2][4][4];
    #pragma unroll
    for (int mt = 0; mt < 2; mt++)
        #pragma unroll
        for (int nt = 0; nt < 4; nt++)
            #pragma unroll
            for (int j = 0; j < 4; j++) c[mt][nt][j] = 0.f;

    const int rA = warpM * 32 + (lane >> 2);
    const int nB = warpN * 32 + (lane >> 2);
    const int kq = lane & 3;

    #pragma unroll
    for (int ks = 0; ks < 16; ks++) {
        const int k0 = ks * 8 + kq;
        uint32_t a[2][4], b[4][2];
        #pragma unroll
        for (int mt = 0; mt < 2; mt++) {
            int r = rA + mt * 16;
            a[mt][0] = As[r * ASTRIDE + k0];
            a[mt][1] = As[(r + 8) * ASTRIDE + k0];
            a[mt][2] = As[r * ASTRIDE + k0 + 4];
            a[mt][3] = As[(r + 8) * ASTRIDE + k0 + 4];
        }
        #pragma unroll
        for (int nt = 0; nt < 4; nt++) {
            int n = nB + nt * 8;
            b[nt][0] = Bs[n * ASTRIDE + k0];
            b[nt][1] = Bs[n * ASTRIDE + k0 + 4];
        }
        #pragma unroll
        for (int mt = 0; mt < 2; mt++)
            #pragma unroll
            for (int nt = 0; nt < 4; nt++)
                mma16n8k8(c[mt][nt], a[mt], b[nt]);
    }

    // ---- epilogue: block column tile is entirely yl or entirely yr ----
    const bool isl = (col0 < dout);   // uniform per block (dout multiple of 64)
    #pragma unroll
    for (int mt = 0; mt < 2; mt++) {
        int r_lo = row0 + warpM * 32 + mt * 16 + (lane >> 2);
        #pragma unroll
        for (int nt = 0; nt < 4; nt++) {
            int col = col0 + warpN * 32 + nt * 8 + 2 * (lane & 3);
            if (isl) {
                if (r_lo < M)
                    *(__half2*)&g_yl[r_lo * dout + col] =
                        __floats2half2_rn(c[mt][nt][0], c[mt][nt][1]);
                if (r_lo + 8 < M)
                    *(__half2*)&g_yl[(r_lo + 8) * dout + col] =
                        __floats2half2_rn(c[mt][nt][2], c[mt][nt][3]);
            } else {
                int cc = col - dout;
                if (r_lo < M)
                    *(float2*)&g_yr[r_lo * dout + cc] = make_float2(c[mt][nt][0], c[mt][nt][1]);
                if (r_lo + 8 < M)
                    *(float2*)&g_yr[(r_lo + 8) * dout + cc] = make_float2(c[mt][nt][2], c[mt][nt][3]);
            }
        }
    }
}

// ================= fused aggregation epilogue =================
// HQ = DOUT/4 lanes per node; lane q owns 4 features (8 B of fp16 per edge).
__device__ __forceinline__ void add4h(float* a, uint2 u) {
    __half2 h0 = *(__half2*)&u.x;
    __half2 h1 = *(__half2*)&u.y;
    float2 f0 = __half22float2(h0);
    float2 f1 = __half22float2(h1);
    a[0] += f0.x; a[1] += f0.y; a[2] += f1.x; a[3] += f1.y;
}

template <int DOUT>
__global__ void agg_kernel(const float* __restrict__ bl, const float* __restrict__ bs,
                           float* __restrict__ outp, int N, int do_relu) {
    const int HQ = DOUT / 4;
    int gt = blockIdx.x * blockDim.x + threadIdx.x;
    int n  = gt / HQ;
    int q  = gt & (HQ - 1);
    if (n >= N) return;

    int beg = g_rowptr[n];
    int end = g_rowptr[n + 1];
    const uint2* YL = (const uint2*)g_yl;

    float a0[4] = {0.f, 0.f, 0.f, 0.f};
    float a1[4] = {0.f, 0.f, 0.f, 0.f};
    int j = beg;
    for (; j + 1 < end; j += 2) {
        uint2 u0 = YL[g_srcs[j] * HQ + q];
        uint2 u1 = YL[g_srcs[j + 1] * HQ + q];
        add4h(a0, u0);
        add4h(a1, u1);
    }
    if (j < end) add4h(a0, YL[g_srcs[j] * HQ + q]);
    #pragma unroll
    for (int k = 0; k < 4; k++) a0[k] += a1[k];

    float inv = g_inv[n];
    float4 yr = ((const float4*)g_yr)[n * HQ + q];
    float4 b1 = ((const float4*)bl)[q];
    float4 b2 = ((const float4*)bs)[q];
    float4 o;
    o.x = fmaf(a0[0], inv, yr.x) + b1.x + b2.x;
    o.y = fmaf(a0[1], inv, yr.y) + b1.y + b2.y;
    o.z = fmaf(a0[2], inv, yr.z) + b1.z + b2.z;
    o.w = fmaf(a0[3], inv, yr.w) + b1.w + b2.w;
    if (do_relu) {
        o.x = fmaxf(o.x, 0.f); o.y = fmaxf(o.y, 0.f);
        o.z = fmaxf(o.z, 0.f); o.w = fmaxf(o.w, 0.f);
    }
    float4* O = outp ? (float4*)outp : (float4*)g_h;
    O[n * HQ + q] = o;
}

// ================= host launch =================
extern "C" void kernel_launch(void* const* d_in, const int* in_sizes, int n_in,
                              void* d_out, int out_size) {
    const float* x  = (const float*)d_in[0];
    const void*  ei = d_in[1];
    const float* Wl[3] = {(const float*)d_in[4],  (const float*)d_in[9],  (const float*)d_in[14]};
    const float* bl[3] = {(const float*)d_in[5],  (const float*)d_in[10], (const float*)d_in[15]};
    const float* Wr[3] = {(const float*)d_in[6],  (const float*)d_in[11], (const float*)d_in[16]};
    const float* Ws[3] = {(const float*)d_in[7],  (const float*)d_in[12], (const float*)d_in[17]};
    const float* bs[3] = {(const float*)d_in[8],  (const float*)d_in[13], (const float*)d_in[18]};

    int N = in_sizes[0] / 128;
    int E = in_sizes[1] / 2;

    cudaFuncSetAttribute(mma_gemm_kernel, cudaFuncAttributeMaxDynamicSharedMemorySize, GSM_BYTES);

    // ---- weight prep (layer-invariant) + CSR build ----
    wcat_all_kernel<<<(640 * 128 + 255) / 256, 256>>>(Wl[0], Wr[0], Ws[0],
                                                      Wl[1], Wr[1], Ws[1],
                                                      Wl[2], Wr[2], Ws[2]);
    probe_kernel<<<1, 256>>>(ei, E, N);
    zero_deg_kernel<<<(N + 255) / 256, 256>>>(N);
    cnt_kernel<<<(E + 255) / 256, 256>>>(ei, E, N);
    int nb = (N + SCAN_BLK - 1) / SCAN_BLK;
    scan1_kernel<<<nb, SCAN_BLK>>>(N);
    scan2_kernel<<<1, SCAN_BLK>>>(nb);
    scan3_kernel<<<nb, SCAN_BLK>>>(N);
    fill_kernel<<<(E + 255) / 256, 256>>>(ei, E, N);

    const int douts[3] = {128, 128, 64};
    const int wrow0s[3] = {0, 256, 512};
    for (int L = 0; L < 3; L++) {
        int dout = douts[L];
        int nc   = 2 * dout;

        dim3 gg((N + 127) / 128, nc / 64);
        mma_gemm_kernel<<<gg, 256, GSM_BYTES>>>(L == 0 ? x : nullptr, N, dout, wrow0s[L]);

        float* outp = (L == 2) ? (float*)d_out : nullptr;
        int threads = N * (dout / 4);
        if (dout == 128)
            agg_kernel<128><<<(threads + 255) / 256, 256>>>(bl[L], bs[L], outp, N, 1);
        else
            agg_kernel<64><<<(threads + 255) / 256, 256>>>(bl[L], bs[L], outp, N, 0);
    }
}

// round 9
// speedup vs baseline: 2.6148x; 1.2322x over previous
#include <cuda_runtime.h>
#include <cuda_fp16.h>
#include <cstdint>

#define MAXN 50000
#define MAXE 800000
#define SCAN_BLK 1024
#define NBLK_SCAN ((MAXN + SCAN_BLK - 1) / SCAN_BLK)

// ---- scratch (static device globals; no allocation anywhere) ----
__device__ __half g_yl[MAXN * 128];     // aggregation operand (lin_l path), fp16
__device__ float  g_yr[MAXN * 128];     // residual path (Wr+Ws), fp32
__device__ __half g_h[MAXN * 128];      // hidden activations, fp16
__device__ __half g_wcat[640 * 128];    // B^T all 3 layers, fp16: [nc rows][128 K]
__device__ float  g_inv[MAXN];
__device__ int    g_deg[MAXN];
__device__ int    g_rowptr[MAXN + 1];
__device__ int    g_cursor[MAXN];
__device__ int    g_srcs[MAXE];
__device__ int    g_is64;
__device__ int    g_bsum[NBLK_SCAN + 1];

// ================= fused setup: wcat (fp16) + zero_deg + dtype probe =================
#define WCAT_BLOCKS 320   // 640*128 / 256
__global__ void setup_kernel(const float* __restrict__ Wl0, const float* __restrict__ Wr0, const float* __restrict__ Ws0,
                             const float* __restrict__ Wl1, const float* __restrict__ Wr1, const float* __restrict__ Ws1,
                             const float* __restrict__ Wl2, const float* __restrict__ Wr2, const float* __restrict__ Ws2,
                             const void* __restrict__ ei, int E, int N) {
    int b = blockIdx.x;
    if (b < WCAT_BLOCKS) {
        int i = b * 256 + threadIdx.x;           // i = grow*128 + k
        int grow = i >> 7, k = i & 127;
        const float *Wl, *Wr, *Ws;
        int j, dout;
        if (grow < 256)      { Wl = Wl0; Wr = Wr0; Ws = Ws0; j = grow;       dout = 128; }
        else if (grow < 512) { Wl = Wl1; Wr = Wr1; Ws = Ws1; j = grow - 256; dout = 128; }
        else                 { Wl = Wl2; Wr = Wr2; Ws = Ws2; j = grow - 512; dout = 64;  }
        float v = (j < dout) ? Wl[k * dout + j]
                             : (Wr[k * dout + (j - dout)] + Ws[k * dout + (j - dout)]);
        g_wcat[i] = __float2half_rn(v);
    } else if (b < gridDim.x - 1) {
        int i = (b - WCAT_BLOCKS) * 256 + threadIdx.x;
        if (i < N) g_deg[i] = 0;
    } else {
        __shared__ int s_bad;
        if (threadIdx.x == 0) s_bad = 0;
        __syncthreads();
        const long long* p = (const long long*)ei;
        int nprobe = (E < 1024) ? E : 1024;
        for (int i = threadIdx.x; i < nprobe; i += blockDim.x) {
            long long v = p[i];
            if (v < 0 || v >= (long long)N) s_bad = 1;
        }
        __syncthreads();
        if (threadIdx.x == 0) g_is64 = s_bad ? 0 : 1;
    }
}

__device__ __forceinline__ int edge_at(const void* ei, int E, int pos) {
    if (g_is64) return (int)((const long long*)ei)[pos];
    return ((const int*)ei)[pos];
}

// ================= CSR build (4 edges per thread) =================
__global__ void cnt_kernel(const void* __restrict__ ei, int E, int N) {
    int base = (blockIdx.x * blockDim.x + threadIdx.x) * 4;
    if (base >= E) return;
    if (!g_is64 && (E & 3) == 0 && base + 4 <= E) {
        int4 d = *(const int4*)&((const int*)ei)[E + base];
        if (d.x >= 0 && d.x < N) atomicAdd(&g_deg[d.x], 1);
        if (d.y >= 0 && d.y < N) atomicAdd(&g_deg[d.y], 1);
        if (d.z >= 0 && d.z < N) atomicAdd(&g_deg[d.z], 1);
        if (d.w >= 0 && d.w < N) atomicAdd(&g_deg[d.w], 1);
    } else {
        for (int e = base; e < base + 4 && e < E; e++) {
            int dst = edge_at(ei, E, E + e);
            if (dst >= 0 && dst < N) atomicAdd(&g_deg[dst], 1);
        }
    }
}

__device__ __forceinline__ int block_scan_incl(int v, int* warp_sums) {
    int lane = threadIdx.x & 31, wid = threadIdx.x >> 5;
    int x = v;
    #pragma unroll
    for (int o = 1; o < 32; o <<= 1) {
        int t = __shfl_up_sync(0xFFFFFFFFu, x, o);
        if (lane >= o) x += t;
    }
    if (lane == 31) warp_sums[wid] = x;
    __syncthreads();
    if (wid == 0) {
        int nw = (blockDim.x + 31) >> 5;
        int w = (lane < nw) ? warp_sums[lane] : 0;
        #pragma unroll
        for (int o = 1; o < 32; o <<= 1) {
            int t = __shfl_up_sync(0xFFFFFFFFu, w, o);
            if (lane >= o) w += t;
        }
        warp_sums[lane] = w;
    }
    __syncthreads();
    return x + (wid > 0 ? warp_sums[wid - 1] : 0);
}

__global__ __launch_bounds__(SCAN_BLK, 1)
void scan1_kernel(int n) {
    __shared__ int warp_sums[32];
    int i = blockIdx.x * SCAN_BLK + threadIdx.x;
    int v = (i < n) ? g_deg[i] : 0;
    int incl = block_scan_incl(v, warp_sums);
    if (i < n) g_rowptr[i] = incl - v;
    if (threadIdx.x == SCAN_BLK - 1) g_bsum[blockIdx.x] = incl;
}

__global__ __launch_bounds__(SCAN_BLK, 1)
void scan2_kernel(int nb) {
    __shared__ int warp_sums[32];
    int t = threadIdx.x;
    int v = (t < nb) ? g_bsum[t] : 0;
    int incl = block_scan_incl(v, warp_sums);
    if (t < nb) g_bsum[t] = incl - v;
    if (t == nb - 1) g_bsum[nb] = incl;
}

__global__ __launch_bounds__(SCAN_BLK, 1)
void scan3_kernel(int n) {
    int i = blockIdx.x * SCAN_BLK + threadIdx.x;
    if (i < n) {
        int r = g_rowptr[i] + g_bsum[blockIdx.x];
        g_rowptr[i] = r;
        g_cursor[i] = r;
        g_inv[i] = 1.0f / fmaxf((float)g_deg[i], 1.0f);
    }
    if (blockIdx.x == 0 && threadIdx.x == 0)
        g_rowptr[n] = g_bsum[(n + SCAN_BLK - 1) / SCAN_BLK];
}

__global__ void fill_kernel(const void* __restrict__ ei, int E, int N) {
    int base = (blockIdx.x * blockDim.x + threadIdx.x) * 4;
    if (base >= E) return;
    if (!g_is64 && (E & 3) == 0 && base + 4 <= E) {
        const int* p = (const int*)ei;
        int4 s = *(const int4*)&p[base];
        int4 d = *(const int4*)&p[E + base];
        if (s.x >= 0 && s.x < N && d.x >= 0 && d.x < N) { int q = atomicAdd(&g_cursor[d.x], 1); if (q >= 0 && q < E) g_srcs[q] = s.x; }
        if (s.y >= 0 && s.y < N && d.y >= 0 && d.y < N) { int q = atomicAdd(&g_cursor[d.y], 1); if (q >= 0 && q < E) g_srcs[q] = s.y; }
        if (s.z >= 0 && s.z < N && d.z >= 0 && d.z < N) { int q = atomicAdd(&g_cursor[d.z], 1); if (q >= 0 && q < E) g_srcs[q] = s.z; }
        if (s.w >= 0 && s.w < N && d.w >= 0 && d.w < N) { int q = atomicAdd(&g_cursor[d.w], 1); if (q >= 0 && q < E) g_srcs[q] = s.w; }
    } else {
        for (int e = base; e < base + 4 && e < E; e++) {
            int src = edge_at(ei, E, e);
            int dst = edge_at(ei, E, E + e);
            if (src >= 0 && src < N && dst >= 0 && dst < N) {
                int q = atomicAdd(&g_cursor[dst], 1);
                if (q >= 0 && q < E) g_srcs[q] = src;
            }
        }
    }
}

// ================= fp16 mma.sync GEMM (m16n8k16, fp32 accum) =================
// tile D[128,64] = A[row0:+128, :128] @ wcat[wrow0+col0 :+64, :128]^T
// A smem [128][HS] halves, B smem [64][HS]; HS=136 -> conflict-free fragment LDS.
// epilogue: cols < dout -> g_yl (fp16), else -> g_yr (fp32)
#define HS 136
static constexpr int GSM_BYTES = (128 * HS + 64 * HS) * 2;  // 52224

__device__ __forceinline__ void mma16n8k16(float* c, const uint32_t* a, const uint32_t* b) {
    asm volatile(
        "mma.sync.aligned.m16n8k16.row.col.f32.f16.f16.f32 "
        "{%0,%1,%2,%3}, {%4,%5,%6,%7}, {%8,%9}, {%0,%1,%2,%3};"
        : "+f"(c[0]), "+f"(c[1]), "+f"(c[2]), "+f"(c[3])
        : "r"(a[0]), "r"(a[1]), "r"(a[2]), "r"(a[3]), "r"(b[0]), "r"(b[1]));
}

template <bool A32>
__global__ __launch_bounds__(256, 2)
void mma_gemm_kernel(const float* __restrict__ Ain, int M, int dout, int wrow0) {
    extern __shared__ __half sh[];
    __half* As = sh;              // [128][HS]
    __half* Bs = sh + 128 * HS;   // [64][HS]
    const int tid = threadIdx.x;
    const int warp = tid >> 5;
    const int lane = tid & 31;
    const int warpM = warp & 3;
    const int warpN = warp >> 2;
    const int row0 = blockIdx.x * 128;
    const int col0 = blockIdx.y * 64;

    // ---- load A tile ----
    if (A32) {
        const float4* A4 = (const float4*)Ain;
        #pragma unroll
        for (int i = 0; i < 16; i++) {
            int idx = i * 256 + tid;
            int row = idx >> 5;          // 0..127
            int q   = idx & 31;          // float4 chunk (4 floats)
            float4 v = make_float4(0.f, 0.f, 0.f, 0.f);
            int gr = row0 + row;
            if (gr < M) v = A4[gr * 32 + q];
            __half2 h0 = __floats2half2_rn(v.x, v.y);
            __half2 h1 = __floats2half2_rn(v.z, v.w);
            *(uint2*)&As[row * HS + q * 4] =
                make_uint2(*(uint32_t*)&h0, *(uint32_t*)&h1);
        }
    } else {
        const uint4* H4 = (const uint4*)g_h;     // 8 halves per uint4
        #pragma unroll
        for (int i = 0; i < 8; i++) {
            int idx = i * 256 + tid;
            int row = idx >> 4;          // 0..127
            int q   = idx & 15;          // 8-half chunk
            uint4 v = make_uint4(0u, 0u, 0u, 0u);
            int gr = row0 + row;
            if (gr < M) v = H4[gr * 16 + q];
            *(uint2*)&As[row * HS + q * 8]     = make_uint2(v.x, v.y);
            *(uint2*)&As[row * HS + q * 8 + 4] = make_uint2(v.z, v.w);
        }
    }
    // ---- load B tile (64 rows x 128 halves) ----
    {
        const uint4* W4 = (const uint4*)g_wcat;
        #pragma unroll
        for (int i = 0; i < 4; i++) {
            int idx = i * 256 + tid;
            int row = idx >> 4;          // 0..63
            int q   = idx & 15;
            uint4 v = W4[(wrow0 + col0 + row) * 16 + q];
            *(uint2*)&Bs[row * HS + q * 8]     = make_uint2(v.x, v.y);
            *(uint2*)&Bs[row * HS + q * 8 + 4] = make_uint2(v.z, v.w);
        }
    }
    __syncthreads();

    float c[2][4][4];
    #pragma unroll
    for (int mt = 0; mt < 2; mt++)
        #pragma unroll
        for (int nt = 0; nt < 4; nt++)
            #pragma unroll
            for (int j = 0; j < 4; j++) c[mt][nt][j] = 0.f;

    const int rA = warpM * 32 + (lane >> 2);
    const int nB = warpN * 32 + (lane >> 2);
    const int kh = (lane & 3) * 2;

    #pragma unroll
    for (int ks = 0; ks < 8; ks++) {
        const int k0 = ks * 16 + kh;
        uint32_t a[2][4], b[4][2];
        #pragma unroll
        for (int mt = 0; mt < 2; mt++) {
            int r = rA + mt * 16;
            a[mt][0] = *(const uint32_t*)&As[r * HS + k0];
            a[mt][1] = *(const uint32_t*)&As[(r + 8) * HS + k0];
            a[mt][2] = *(const uint32_t*)&As[r * HS + k0 + 8];
            a[mt][3] = *(const uint32_t*)&As[(r + 8) * HS + k0 + 8];
        }
        #pragma unroll
        for (int nt = 0; nt < 4; nt++) {
            int n = nB + nt * 8;
            b[nt][0] = *(const uint32_t*)&Bs[n * HS + k0];
            b[nt][1] = *(const uint32_t*)&Bs[n * HS + k0 + 8];
        }
        #pragma unroll
        for (int mt = 0; mt < 2; mt++)
            #pragma unroll
            for (int nt = 0; nt < 4; nt++)
                mma16n8k16(c[mt][nt], a[mt], b[nt]);
    }

    // ---- epilogue ----
    const bool isl = (col0 < dout);
    #pragma unroll
    for (int mt = 0; mt < 2; mt++) {
        int r_lo = row0 + warpM * 32 + mt * 16 + (lane >> 2);
        #pragma unroll
        for (int nt = 0; nt < 4; nt++) {
            int col = col0 + warpN * 32 + nt * 8 + 2 * (lane & 3);
            if (isl) {
                if (r_lo < M)
                    *(__half2*)&g_yl[r_lo * dout + col] =
                        __floats2half2_rn(c[mt][nt][0], c[mt][nt][1]);
                if (r_lo + 8 < M)
                    *(__half2*)&g_yl[(r_lo + 8) * dout + col] =
                        __floats2half2_rn(c[mt][nt][2], c[mt][nt][3]);
            } else {
                int cc = col - dout;
                if (r_lo < M)
                    *(float2*)&g_yr[r_lo * dout + cc] = make_float2(c[mt][nt][0], c[mt][nt][1]);
                if (r_lo + 8 < M)
                    *(float2*)&g_yr[(r_lo + 8) * dout + cc] = make_float2(c[mt][nt][2], c[mt][nt][3]);
            }
        }
    }
}

// ================= fused aggregation epilogue =================
__device__ __forceinline__ void add4h(float* a, uint2 u) {
    __half2 h0 = *(__half2*)&u.x;
    __half2 h1 = *(__half2*)&u.y;
    float2 f0 = __half22float2(h0);
    float2 f1 = __half22float2(h1);
    a[0] += f0.x; a[1] += f0.y; a[2] += f1.x; a[3] += f1.y;
}

// OUT16: write g_h (fp16, with relu); else write outp (fp32, no relu)
template <int DOUT, bool OUT16>
__global__ void agg_kernel(const float* __restrict__ bl, const float* __restrict__ bs,
                           float* __restrict__ outp, int N) {
    const int HQ = DOUT / 4;
    int gt = blockIdx.x * blockDim.x + threadIdx.x;
    int n  = gt / HQ;
    int q  = gt & (HQ - 1);
    if (n >= N) return;

    int beg = g_rowptr[n];
    int end = g_rowptr[n + 1];
    const uint2* YL = (const uint2*)g_yl;

    float a0[4] = {0.f, 0.f, 0.f, 0.f};
    float a1[4] = {0.f, 0.f, 0.f, 0.f};
    int j = beg;
    for (; j + 1 < end; j += 2) {
        uint2 u0 = YL[g_srcs[j] * HQ + q];
        uint2 u1 = YL[g_srcs[j + 1] * HQ + q];
        add4h(a0, u0);
        add4h(a1, u1);
    }
    if (j < end) add4h(a0, YL[g_srcs[j] * HQ + q]);
    #pragma unroll
    for (int k = 0; k < 4; k++) a0[k] += a1[k];

    float inv = g_inv[n];
    float4 yr = ((const float4*)g_yr)[n * HQ + q];
    float4 b1 = ((const float4*)bl)[q];
    float4 b2 = ((const float4*)bs)[q];
    float4 o;
    o.x = fmaf(a0[0], inv, yr.x) + b1.x + b2.x;
    o.y = fmaf(a0[1], inv, yr.y) + b1.y + b2.y;
    o.z = fmaf(a0[2], inv, yr.z) + b1.z + b2.z;
    o.w = fmaf(a0[3], inv, yr.w) + b1.w + b2.w;
    if (OUT16) {
        o.x = fmaxf(o.x, 0.f); o.y = fmaxf(o.y, 0.f);
        o.z = fmaxf(o.z, 0.f); o.w = fmaxf(o.w, 0.f);
        __half2 h0 = __floats2half2_rn(o.x, o.y);
        __half2 h1 = __floats2half2_rn(o.z, o.w);
        *(uint2*)&g_h[n * DOUT + q * 4] = make_uint2(*(uint32_t*)&h0, *(uint32_t*)&h1);
    } else {
        ((float4*)outp)[n * HQ + q] = o;
    }
}

// ================= host launch =================
extern "C" void kernel_launch(void* const* d_in, const int* in_sizes, int n_in,
                              void* d_out, int out_size) {
    const float* x  = (const float*)d_in[0];
    const void*  ei = d_in[1];
    const float* Wl[3] = {(const float*)d_in[4],  (const float*)d_in[9],  (const float*)d_in[14]};
    const float* bl[3] = {(const float*)d_in[5],  (const float*)d_in[10], (const float*)d_in[15]};
    const float* Wr[3] = {(const float*)d_in[6],  (const float*)d_in[11], (const float*)d_in[16]};
    const float* Ws[3] = {(const float*)d_in[7],  (const float*)d_in[12], (const float*)d_in[17]};
    const float* bs[3] = {(const float*)d_in[8],  (const float*)d_in[13], (const float*)d_in[18]};

    int N = in_sizes[0] / 128;
    int E = in_sizes[1] / 2;

    cudaFuncSetAttribute(mma_gemm_kernel<true>,  cudaFuncAttributeMaxDynamicSharedMemorySize, GSM_BYTES);
    cudaFuncSetAttribute(mma_gemm_kernel<false>, cudaFuncAttributeMaxDynamicSharedMemorySize, GSM_BYTES);

    // ---- setup (wcat + zero + probe) + CSR build ----
    int setup_grid = WCAT_BLOCKS + (N + 255) / 256 + 1;
    setup_kernel<<<setup_grid, 256>>>(Wl[0], Wr[0], Ws[0], Wl[1], Wr[1], Ws[1],
                                      Wl[2], Wr[2], Ws[2], ei, E, N);
    int egrid = (E / 4 + 256) / 256 + 1;
    cnt_kernel<<<egrid, 256>>>(ei, E, N);
    int nb = (N + SCAN_BLK - 1) / SCAN_BLK;
    scan1_kernel<<<nb, SCAN_BLK>>>(N);
    scan2_kernel<<<1, SCAN_BLK>>>(nb);
    scan3_kernel<<<nb, SCAN_BLK>>>(N);
    fill_kernel<<<egrid, 256>>>(ei, E, N);

    const int douts[3]  = {128, 128, 64};
    const int wrow0s[3] = {0, 256, 512};
    for (int L = 0; L < 3; L++) {
        int dout = douts[L];
        int nc   = 2 * dout;

        dim3 gg((N + 127) / 128, nc / 64);
        if (L == 0)
            mma_gemm_kernel<true><<<gg, 256, GSM_BYTES>>>(x, N, dout, wrow0s[L]);
        else
            mma_gemm_kernel<false><<<gg, 256, GSM_BYTES>>>(nullptr, N, dout, wrow0s[L]);

        int threads = N * (dout / 4);
        if (L < 2)
            agg_kernel<128, true><<<(threads + 255) / 256, 256>>>(bl[L], bs[L], nullptr, N);
        else
            agg_kernel<64, false><<<(threads + 255) / 256, 256>>>(bl[L], bs[L], (float*)d_out, N);
    }
}